// round 2
// baseline (speedup 1.0000x reference)
#include <cuda_runtime.h>

#define N_VERTICES 1000000
#define N_EDGES    16000000

// Scratch accumulator. Zero-initialized at module load; finalize_kernel
// resets it to zero after consuming it, so every invocation (correctness
// run and each graph replay) starts from a clean state.
__device__ float g_cbar[N_VERTICES];

// 4 edges per thread: 1x int4 index load (int32 indices!) + 2x float4
// edge_attr loads. N_EDGES = 16M is divisible by 4, so no tail handling.
// NOTE: JAX default config has x64 disabled, so the "int64" index array is
// actually int32 on device. Reading it as int64 was R1's correctness bug.
__global__ void scatter_kernel(const int* __restrict__ src_idx,
                               const float* __restrict__ edge_attr) {
    unsigned t = blockIdx.x * blockDim.x + threadIdx.x;   // t in [0, 4M)
    const int4*   idx4 = (const int4*)src_idx;
    const float4* ea4  = (const float4*)edge_attr;

    int4   i0123 = idx4[t];            // indices of edges 4t .. 4t+3
    float4 e01   = ea4[2u * t];        // edges 4t,4t+1: (c0a,c0b,c1a,c1b)
    float4 e23   = ea4[2u * t + 1u];   // edges 4t+2,4t+3

    atomicAdd(&g_cbar[i0123.x], e01.y);
    atomicAdd(&g_cbar[i0123.y], e01.w);
    atomicAdd(&g_cbar[i0123.z], e23.y);
    atomicAdd(&g_cbar[i0123.w], e23.w);
}

// out[i] = [b_i, x_i, b_i - cbar_i]; also reset accumulator for next replay.
__global__ void finalize_kernel(const float* __restrict__ vertex_attr,
                                float* __restrict__ out) {
    unsigned i = blockIdx.x * blockDim.x + threadIdx.x;
    if (i < N_VERTICES) {
        float2 v = ((const float2*)vertex_attr)[i];   // (b_i, x_i)
        float  c = g_cbar[i];
        g_cbar[i] = 0.0f;
        out[3u * i + 0u] = v.x;
        out[3u * i + 1u] = v.y;
        out[3u * i + 2u] = v.x - c;
    }
}

extern "C" void kernel_launch(void* const* d_in, const int* in_sizes, int n_in,
                              void* d_out, int out_size) {
    // Inputs per metadata order (JAX x64 disabled => "int64" arrays are int32):
    // 0: vertex_attr  (1M x 2)  f32
    // 1: edgeij_pair  (2 x 16M) int32  -- row 0 = source indices (first 16M)
    // 2: edge_attr    (16M x 2) f32
    // 3: g            (1 x 1)   f32    -- unused
    // 4: batch        (1M,)     int32  -- unused
    const float* vertex_attr = (const float*)d_in[0];
    const int*   edge_src    = (const int*)d_in[1];   // row 0
    const float* edge_attr   = (const float*)d_in[2];
    float*       out         = (float*)d_out;

    // Scatter: 16M edges / 4 per thread = 4M threads
    {
        const int threads = 256;
        const int blocks  = (N_EDGES / 4) / threads;  // 16384
        scatter_kernel<<<blocks, threads>>>(edge_src, edge_attr);
    }
    // Finalize
    {
        const int threads = 256;
        const int blocks  = (N_VERTICES + threads - 1) / threads;
        finalize_kernel<<<blocks, threads>>>(vertex_attr, out);
    }
}

// round 3
// speedup vs baseline: 1.0191x; 1.0191x over previous
#include <cuda_runtime.h>

#define N_VERTICES 1000000
#define N_EDGES    16000000

// Scratch accumulator. Zero-initialized at module load; finalize_kernel
// resets it to zero after consuming it, so every invocation (correctness
// run and each graph replay) starts from a clean state.
__device__ float g_cbar[N_VERTICES];

// Scatter: 4 edges per thread (int4 index load + 2x float4 edge_attr loads).
// The scatter is bound by SM-side REDG issue (~1.29 cyc/lane spread-address),
// leaving DRAM mostly idle — so the first 250K threads additionally copy the
// (b, x) columns into out, hiding that traffic under the atomic floor.
__global__ void scatter_kernel(const int* __restrict__ src_idx,
                               const float* __restrict__ edge_attr,
                               const float* __restrict__ vertex_attr,
                               float* __restrict__ out) {
    unsigned t = blockIdx.x * blockDim.x + threadIdx.x;   // t in [0, 4M)
    const int4*   idx4 = (const int4*)src_idx;
    const float4* ea4  = (const float4*)edge_attr;

    int4   i0123 = idx4[t];            // indices of edges 4t .. 4t+3
    float4 e01   = ea4[2u * t];        // edges 4t,4t+1: (c0a,c0b,c1a,c1b)
    float4 e23   = ea4[2u * t + 1u];   // edges 4t+2,4t+3

    atomicAdd(&g_cbar[i0123.x], e01.y);
    atomicAdd(&g_cbar[i0123.y], e01.w);
    atomicAdd(&g_cbar[i0123.z], e23.y);
    atomicAdd(&g_cbar[i0123.w], e23.w);

    // Piggy-backed copy of b,x for 4 vertices per thread (250K threads).
    if (t < N_VERTICES / 4) {
        const float4* va4 = (const float4*)vertex_attr;
        float4 v01 = va4[2u * t];        // (b0, x0, b1, x1)
        float4 v23 = va4[2u * t + 1u];   // (b2, x2, b3, x3)
        unsigned base = 12u * t;
        out[base + 0u]  = v01.x;  out[base + 1u]  = v01.y;
        out[base + 3u]  = v01.z;  out[base + 4u]  = v01.w;
        out[base + 6u]  = v23.x;  out[base + 7u]  = v23.y;
        out[base + 9u]  = v23.z;  out[base + 10u] = v23.w;
    }
}

// Finalize: 4 vertices per thread. Writes only the r_i column
// (out[3i+2] = b_i - cbar_i) and resets the accumulator for the next replay.
__global__ void finalize_kernel(const float* __restrict__ vertex_attr,
                                float* __restrict__ out) {
    unsigned q = blockIdx.x * blockDim.x + threadIdx.x;   // q in [0, 250K)
    if (q < N_VERTICES / 4) {
        const float4* va4 = (const float4*)vertex_attr;
        float4 v01 = va4[2u * q];        // (b0, x0, b1, x1)
        float4 v23 = va4[2u * q + 1u];   // (b2, x2, b3, x3)

        float4* c4p = (float4*)&g_cbar[4u * q];
        float4 c = *c4p;
        *c4p = make_float4(0.0f, 0.0f, 0.0f, 0.0f);

        unsigned base = 12u * q;
        out[base + 2u]  = v01.x - c.x;
        out[base + 5u]  = v01.z - c.y;
        out[base + 8u]  = v23.x - c.z;
        out[base + 11u] = v23.z - c.w;
    }
}

extern "C" void kernel_launch(void* const* d_in, const int* in_sizes, int n_in,
                              void* d_out, int out_size) {
    // Inputs per metadata order (JAX x64 disabled => "int64" arrays are int32):
    // 0: vertex_attr  (1M x 2)  f32
    // 1: edgeij_pair  (2 x 16M) int32  -- row 0 = source indices (first 16M)
    // 2: edge_attr    (16M x 2) f32
    // 3: g            (1 x 1)   f32    -- unused
    // 4: batch        (1M,)     int32  -- unused
    const float* vertex_attr = (const float*)d_in[0];
    const int*   edge_src    = (const int*)d_in[1];   // row 0
    const float* edge_attr   = (const float*)d_in[2];
    float*       out         = (float*)d_out;

    // Scatter (+ fused b,x copy): 16M edges / 4 per thread = 4M threads
    {
        const int threads = 256;
        const int blocks  = (N_EDGES / 4) / threads;  // 16384
        scatter_kernel<<<blocks, threads>>>(edge_src, edge_attr, vertex_attr, out);
    }
    // Finalize: 250K threads, 4 vertices each
    {
        const int threads = 256;
        const int blocks  = (N_VERTICES / 4 + threads - 1) / threads;  // 977
        finalize_kernel<<<blocks, threads>>>(vertex_attr, out);
    }
}

// round 4
// speedup vs baseline: 1.0368x; 1.0173x over previous
#include <cuda_runtime.h>

#define N_VERTICES 1000000
#define N_EDGES    16000000

// Scratch accumulator. Zero-initialized at module load; finalize_kernel
// resets it to zero after consuming it, so every graph replay starts clean.
__device__ float g_cbar[N_VERTICES];

// Scatter: 4 edges per thread (int4 index load + 2x float4 edge_attr loads).
// 16M spread-address fp32 REDs ~= chip-wide L2 atomic ceiling (~200 Gop/s).
// Keep this kernel minimal — any extra work here regressed in R3.
__global__ void scatter_kernel(const int* __restrict__ src_idx,
                               const float* __restrict__ edge_attr) {
    unsigned t = blockIdx.x * blockDim.x + threadIdx.x;   // t in [0, 4M)
    const int4*   idx4 = (const int4*)src_idx;
    const float4* ea4  = (const float4*)edge_attr;

    int4   i0123 = idx4[t];            // indices of edges 4t .. 4t+3
    float4 e01   = ea4[2u * t];        // edges 4t,4t+1: (c0a,c0b,c1a,c1b)
    float4 e23   = ea4[2u * t + 1u];   // edges 4t+2,4t+3

    atomicAdd(&g_cbar[i0123.x], e01.y);
    atomicAdd(&g_cbar[i0123.y], e01.w);
    atomicAdd(&g_cbar[i0123.z], e23.y);
    atomicAdd(&g_cbar[i0123.w], e23.w);
}

// Finalize: 2 vertices per thread, 500K threads.
// Independent loads (float4 vertex pair + float2 cbar pair), full-row writes
// (b,x,r per vertex -> 3 aligned float2 stores, full sectors), and reset of
// the accumulator for the next replay.
__global__ void finalize_kernel(const float* __restrict__ vertex_attr,
                                float* __restrict__ out) {
    unsigned q = blockIdx.x * blockDim.x + threadIdx.x;   // q in [0, 500K)
    if (q < N_VERTICES / 2) {
        float4 v = ((const float4*)vertex_attr)[q];       // (b0,x0,b1,x1)

        float2* cp = (float2*)&g_cbar[2u * q];
        float2 c = *cp;
        *cp = make_float2(0.0f, 0.0f);

        float2* o2 = (float2*)(out + 6u * (unsigned long long)q);
        o2[0] = make_float2(v.x, v.y);          // b0, x0
        o2[1] = make_float2(v.x - c.x, v.z);    // r0, b1
        o2[2] = make_float2(v.w, v.z - c.y);    // x1, r1
    }
}

extern "C" void kernel_launch(void* const* d_in, const int* in_sizes, int n_in,
                              void* d_out, int out_size) {
    // Inputs per metadata order (JAX x64 disabled => "int64" arrays are int32):
    // 0: vertex_attr  (1M x 2)  f32
    // 1: edgeij_pair  (2 x 16M) int32  -- row 0 = source indices (first 16M)
    // 2: edge_attr    (16M x 2) f32
    // 3: g            (1 x 1)   f32    -- unused
    // 4: batch        (1M,)     int32  -- unused
    const float* vertex_attr = (const float*)d_in[0];
    const int*   edge_src    = (const int*)d_in[1];   // row 0
    const float* edge_attr   = (const float*)d_in[2];
    float*       out         = (float*)d_out;

    // Scatter: 16M edges / 4 per thread = 4M threads
    {
        const int threads = 256;
        const int blocks  = (N_EDGES / 4) / threads;  // 16384
        scatter_kernel<<<blocks, threads>>>(edge_src, edge_attr);
    }
    // Finalize: 500K threads, 2 vertices each
    {
        const int threads = 256;
        const int blocks  = (N_VERTICES / 2 + threads - 1) / threads;  // 1954
        finalize_kernel<<<blocks, threads>>>(vertex_attr, out);
    }
}

// round 7
// speedup vs baseline: 1.0574x; 1.0199x over previous
#include <cuda_runtime.h>

#define N_VERTICES 1000000
#define N_EDGES    16000000

// Scratch accumulator. Zero-initialized at module load; finalize_kernel
// resets it to zero after consuming it, so every graph replay starts clean.
__device__ float g_cbar[N_VERTICES];

// Scatter: 8 edges per thread (2x int4 index loads + 4x float4 edge_attr
// loads + 8 REDs). Bound by the SM-side REDG issue floor
// (~1.29 cyc/lane spread-address -> ~79us for 16M lanes on 148 SMs).
// Launch config: 128 threads x 15625 blocks = exactly 2M threads
// (N_EDGES/8 = 2,000,000 is NOT divisible by 256 — R6's correctness bug).
__global__ void __launch_bounds__(128, 16)
scatter_kernel(const int* __restrict__ src_idx,
               const float* __restrict__ edge_attr) {
    unsigned t = blockIdx.x * blockDim.x + threadIdx.x;   // t in [0, 2,000,000)
    const int4*   idx4 = (const int4*)src_idx;
    const float4* ea4  = (const float4*)edge_attr;

    int4   ia = idx4[2u * t];          // edges 8t .. 8t+3
    int4   ib = idx4[2u * t + 1u];     // edges 8t+4 .. 8t+7
    float4 e0 = ea4[4u * t];           // edges 8t,8t+1
    float4 e1 = ea4[4u * t + 1u];      // edges 8t+2,8t+3
    float4 e2 = ea4[4u * t + 2u];      // edges 8t+4,8t+5
    float4 e3 = ea4[4u * t + 3u];      // edges 8t+6,8t+7

    atomicAdd(&g_cbar[ia.x], e0.y);
    atomicAdd(&g_cbar[ia.y], e0.w);
    atomicAdd(&g_cbar[ia.z], e1.y);
    atomicAdd(&g_cbar[ia.w], e1.w);
    atomicAdd(&g_cbar[ib.x], e2.y);
    atomicAdd(&g_cbar[ib.y], e2.w);
    atomicAdd(&g_cbar[ib.z], e3.y);
    atomicAdd(&g_cbar[ib.w], e3.w);
}

// Finalize: 4 vertices per thread, 250K threads.
// 3 independent 16B loads, 4 aligned 16B stores. out base = 48*q bytes
// (16B-aligned), so rows pack exactly into 3 float4 stores.
__global__ void __launch_bounds__(256, 8)
finalize_kernel(const float* __restrict__ vertex_attr,
                float* __restrict__ out) {
    unsigned q = blockIdx.x * blockDim.x + threadIdx.x;   // q in [0, 250K)
    if (q < N_VERTICES / 4) {
        const float4* va4 = (const float4*)vertex_attr;
        float4 v01 = va4[2u * q];        // (b0,x0,b1,x1)
        float4 v23 = va4[2u * q + 1u];   // (b2,x2,b3,x3)

        float4* cp = (float4*)&g_cbar[4u * q];
        float4 c = *cp;
        *cp = make_float4(0.0f, 0.0f, 0.0f, 0.0f);

        float4* o4 = (float4*)(out + 12u * (unsigned long long)q);
        o4[0] = make_float4(v01.x, v01.y, v01.x - c.x, v01.z);  // b0,x0,r0,b1
        o4[1] = make_float4(v01.w, v01.z - c.y, v23.x, v23.y);  // x1,r1,b2,x2
        o4[2] = make_float4(v23.x - c.z, v23.z, v23.w, v23.z - c.w); // r2,b3,x3,r3
    }
}

extern "C" void kernel_launch(void* const* d_in, const int* in_sizes, int n_in,
                              void* d_out, int out_size) {
    // Inputs per metadata order (JAX x64 disabled => "int64" arrays are int32):
    // 0: vertex_attr  (1M x 2)  f32
    // 1: edgeij_pair  (2 x 16M) int32  -- row 0 = source indices (first 16M)
    // 2: edge_attr    (16M x 2) f32
    // 3: g            (1 x 1)   f32    -- unused
    // 4: batch        (1M,)     int32  -- unused
    const float* vertex_attr = (const float*)d_in[0];
    const int*   edge_src    = (const int*)d_in[1];   // row 0
    const float* edge_attr   = (const float*)d_in[2];
    float*       out         = (float*)d_out;

    // Scatter: 16M edges / 8 per thread = 2,000,000 threads = 128 x 15625 exact
    {
        const int threads = 128;
        const int blocks  = (N_EDGES / 8) / threads;  // 15625, exact
        scatter_kernel<<<blocks, threads>>>(edge_src, edge_attr);
    }
    // Finalize: 250K threads, 4 vertices each
    {
        const int threads = 256;
        const int blocks  = (N_VERTICES / 4 + threads - 1) / threads;  // 977
        finalize_kernel<<<blocks, threads>>>(vertex_attr, out);
    }
}